// round 14
// baseline (speedup 1.0000x reference)
#include <cuda_runtime.h>
#include <math.h>

#define DD 128
#define WIN 15
#define WW (2*WIN+1)          // 31
#define MAXB 4
#define MAXS 4096
#define TILE 16
#define TR2 (TILE + WIN)      // 31 smem rows
#define RPAD 132
#define RP4  (RPAD/4)         // 33

__device__ float g_dotf[(size_t)MAXB*MAXS*WIN];   // forward dots [row][15]
__device__ int   g_spk[MAXB*MAXS];
__device__ float g_band[(size_t)MAXB*MAXS*WW];
__device__ float g_dinv[MAXB*MAXS];
__device__ int   g_tflag[(MAXB*MAXS)/TILE];       // tile done flags
__device__ int   g_rflag[MAXB*MAXS];              // row (band+dinv) done flags

__device__ __forceinline__ void stg256_cs(float* p, const float4& a, const float4& b) {
    asm volatile("st.global.cs.v8.f32 [%0], {%1,%2,%3,%4,%5,%6,%7,%8};"
                 :: "l"(p),
                    "f"(a.x), "f"(a.y), "f"(a.z), "f"(a.w),
                    "f"(b.x), "f"(b.y), "f"(b.z), "f"(b.w)
                 : "memory");
}

// fast acos: Abramowitz-Stegun 4.4.45, |err| <= 6.7e-5 rad
__device__ __forceinline__ float angular_weight(float c) {
    float ax = fabsf(c);
    float s = sqrtf(fmaxf(1.f - ax, 0.f));
    float p = s * (1.5707288f + ax * (-0.2121144f + ax * (0.0742610f - ax * 0.0187293f)));
    float ac = (c >= 0.f) ? p : (3.14159265358979f - p);
    return 1.f - ac * 0.31830988618379067f;
}

__global__ __launch_bounds__(256)
void reset_kernel(int nt, int nr) {
    int t = blockIdx.x * blockDim.x + threadIdx.x;
    if (t < nt) g_tflag[t] = 0;
    if (t < nr) g_rflag[t] = 0;
}

// ---- patch one row q: writes the band-overlapping chunks (disjoint sectors vs zero) ----
__device__ __forceinline__ void patch_row(float* __restrict__ out, int q, int S, int lane) {
    int bq = q / S, iq = q % S;

    // spin: need g_rflag for rows bq*S + j, j in window (lane per neighbor)
    int j = iq - WIN + lane;
    bool need = (lane < WW) && (j >= 0) && (j < S);
    int u = bq * S + j;
    bool done = !need;
    while (!__all_sync(0xffffffffu, done)) {
        if (!done) done = (atomicAdd(&g_rflag[u], 0) != 0);
        if (!__all_sync(0xffffffffu, done)) __nanosleep(64);
    }
    __threadfence();

    int jstart = max(iq - WIN, 0);
    int jend   = min(iq + WIN, S - 1);
    int p0 = (jstart >> 3) << 3;
    int p1 = ((jend >> 3) << 3) + 7;

    float dq = g_dinv[q];
    const float* bp = g_band + (size_t)q * WW;
    float* orow = out + (size_t)q * S;
#pragma unroll
    for (int pass = 0; pass < 2; pass++) {
        int j2 = p0 + pass * 32 + lane;
        if (j2 <= p1) {
            int d = j2 - (iq - WIN);
            float v = (d >= 0 && d < WW)
                      ? bp[d] * dq * g_dinv[bq * S + j2] : 0.f;
            orow[j2] = v;
        }
    }
}

__global__ __launch_bounds__(256)
void mega_kernel(const float* __restrict__ x,
                 const float* __restrict__ qmask,
                 const int* __restrict__ dia_len,
                 float* __restrict__ out,
                 int B, int S, int NSPK) {
    __shared__ float sx[TR2 * RPAD];

    int n = B * S;
    int NT = n / TILE;
    int NCH = n / TILE;                       // row chunks of 16
    int bid = blockIdx.x;
    int lane = threadIdx.x & 31;
    int warp = threadIdx.x >> 5;

    // ---- role decode: [T0][T1] ([16 rows][tile c+2]) x NCH [15 patch-only] ----
    int tile = -1, r = -1, qonly = -1;
    if (bid < 2) {
        tile = bid;
    } else if (bid < 2 + 17 * NCH) {
        int c = (bid - 2) / 17, m = (bid - 2) % 17;
        if (m < 16) r = c * TILE + m;
        else { int t = c + 2; if (t < NT) tile = t; }
    } else {
        qonly = n - WIN + (bid - (2 + 17 * NCH));   // rows n-15..n-1
    }

    // ================= tile block: dotprep =================
    if (tile >= 0) {
        int b  = tile / (S / TILE);
        int i0 = (tile % (S / TILE)) * TILE;
        int base = b * S;
        float4* sx4 = (float4*)sx;
        const float4* x4g = (const float4*)(x + (size_t)base * DD);

        {
            int sub = threadIdx.x & 7;
            int rr = threadIdx.x >> 3;
            int gr = i0 + rr;
            bool inb = (rr < TR2) && (gr < S);
            float4 v[4];
            float ss = 0.f;
            if (inb) {
#pragma unroll
                for (int k = 0; k < 4; k++) {
                    v[k] = x4g[(size_t)gr * (DD/4) + sub * 4 + k];
                    ss += v[k].x * v[k].x + v[k].y * v[k].y
                        + v[k].z * v[k].z + v[k].w * v[k].w;
                }
            } else {
#pragma unroll
                for (int k = 0; k < 4; k++) v[k] = make_float4(0.f, 0.f, 0.f, 0.f);
            }
#pragma unroll
            for (int off = 4; off; off >>= 1)
                ss += __shfl_xor_sync(0xffffffffu, ss, off);
            float inv = 1.f / fmaxf(sqrtf(ss), 1e-8f);
            if (rr < TR2) {
#pragma unroll
                for (int k = 0; k < 4; k++) {
                    v[k].x *= inv; v[k].y *= inv; v[k].z *= inv; v[k].w *= inv;
                    sx4[rr * RP4 + sub * 4 + k] = v[k];
                }
            }
            if (threadIdx.x < TILE) {
                int g2 = i0 + threadIdx.x;
                if (g2 < S) {
                    const float* q = qmask + ((size_t)g2 * B + b) * NSPK;
                    float best = q[0]; int bi = 0;
                    for (int k = 1; k < NSPK; k++) {
                        float vq = q[k];
                        if (vq > best) { best = vq; bi = k; }
                    }
                    g_spk[base + g2] = bi;
                }
            }
        }
        __syncthreads();

        int half = lane >> 4;
        int o = lane & 15;
        int rl = 2 * warp + half;
        int i = i0 + rl;
        bool active = (o < 15) && (i < S);
        int jlc = active ? (rl + 1 + o) : rl;

        float dot = 0.f;
        const float4* xi4 = (float4*)sx + rl * RP4;
        const float4* xj4 = (float4*)sx + jlc * RP4;
#pragma unroll
        for (int k = 0; k < DD/4; k++) {
            float4 a4 = xi4[k];
            float4 b4 = xj4[k];
            dot += a4.x * b4.x + a4.y * b4.y + a4.z * b4.z + a4.w * b4.w;
        }
        if (active)
            g_dotf[(size_t)(base + i) * WIN + o] = dot;

        __threadfence();
        __syncthreads();
        if (threadIdx.x == 0) atomicExch(&g_tflag[tile], 1);
        return;
    }

    // ================= trailing patch-only block =================
    if (qonly >= 0) {
        if (warp == 0) patch_row(out, qonly, S, lane);
        return;
    }

    // ================= row block: zero + assemble + patch =================
    if (r < 0) return;
    int b = r / S, i = r % S;

    // Phase 1: zero the non-band chunks of row r (all threads)
    {
        float* orow = out + (size_t)r * S;
        int clo = max(i - WIN, 0) >> 3;
        int chi = min(i + WIN, S - 1) >> 3;
        const float4 z = make_float4(0.f, 0.f, 0.f, 0.f);
        int nch = S >> 3;
        for (int c = threadIdx.x; c < nch; c += blockDim.x) {
            if (c < clo || c > chi)
                stg256_cs(orow + (c << 3), z, z);
        }
    }

    // Phase 2: wait for the dot tiles covering this row's window
    {
        int tmin = (b * S + max(i - WIN, 0)) / TILE;
        int tmax = (b * S + min(i + WIN, S - 1)) / TILE;
        if (threadIdx.x == 0) {
            for (int t = tmin; t <= tmax; t++)
                while (atomicAdd(&g_tflag[t], 0) == 0) __nanosleep(64);
            __threadfence();
        }
        __syncthreads();
    }

    // Phase 3 (warp 0): assemble row r -> g_band, g_dinv, flag
    if (warp == 0) {
        int base = b * S;
        int len = dia_len[b];
        bool valid_i = (i < len);
        int j = i - WIN + lane;
        bool inr = (lane < WW) && (j >= 0) && (j < S);

        float dot = 0.f;
        if (lane < WIN) {
            if (j >= 0) dot = g_dotf[(size_t)(base + j) * WIN + (14 - lane)];
        } else if (lane == WIN) {
            dot = 1.f;
        } else if (lane < WW) {
            if (j < S) dot = g_dotf[(size_t)(base + i) * WIN + (lane - 16)];
        }

        int spk_i = g_spk[base + i];
        int spk_j = inr ? g_spk[base + j] : -1;
        bool valid_j = valid_i && inr && (j < len);
        bool same = valid_j && (spk_j == spk_i);
        int cnt = __popc(__ballot_sync(0xffffffffu, same));

        float a = 0.f;
        if (valid_j) {
            float c = fminf(fmaxf(dot, -1.f), 1.f);
            a = angular_weight(c) * ((cnt > 1 && same) ? 2.f : 1.f);
        }
        float deg = a;
#pragma unroll
        for (int off = 16; off; off >>= 1)
            deg += __shfl_xor_sync(0xffffffffu, deg, off);

        if (lane < WW) g_band[(size_t)r * WW + lane] = a;
        if (lane == 0)
            g_dinv[r] = (deg > 0.f) ? rsqrtf(deg) : 1.f;

        __syncwarp();
        __threadfence();
        if (lane == 0) atomicExch(&g_rflag[r], 1);
    }
    // Phase 4 (warp 1): patch row r-15 (deps all at lower-or-equal bids;
    // own row's flag is set by warp 0 concurrently — no barrier between them)
    else if (warp == 1) {
        int q = r - WIN;
        if (q >= 0) patch_row(out, q, S, lane);
    }
}

extern "C" void kernel_launch(void* const* d_in, const int* in_sizes, int n_in,
                              void* d_out, int out_size) {
    const float* x       = (const float*)d_in[0];
    const float* qmask   = (const float*)d_in[1];
    const int*   dia_len = (const int*)d_in[2];
    float* out = (float*)d_out;

    int B = in_sizes[2];
    int S = in_sizes[0] / (B * DD);
    int NSPK = in_sizes[1] / (B * S);
    int n = B * S;
    int NT = n / TILE;

    reset_kernel<<<(n + 255) / 256, 256>>>(NT, n);

    int grid = 2 + 17 * (n / TILE) + WIN;
    mega_kernel<<<grid, 256>>>(x, qmask, dia_len, out, B, S, NSPK);
}

// round 15
// speedup vs baseline: 4.1410x; 4.1410x over previous
#include <cuda_runtime.h>
#include <math.h>

#define DD 128
#define WIN 15
#define WW (2*WIN+1)          // 31
#define CR 64                 // central rows per band block
#define LR (CR + 4*WIN)       // 124 loaded rows  [i0-30, i0+94)
#define DR (CR + 2*WIN)       // 94 dinv rows     [i0-15, i0+79)
#define SR (CR + 3*WIN)       // 109 sdot rows    [i0-30, i0+79)
#define RPAD 132
#define RP4  (RPAD/4)         // 33
#define SMEM_FLOATS (LR*RPAD + SR*WIN + CR*WW + DR + LR)
#define SMEM_BYTES  (SMEM_FLOATS * 4)

__device__ __forceinline__ void stg256_cs(float* p, const float4& a, const float4& b) {
    asm volatile("st.global.cs.v8.f32 [%0], {%1,%2,%3,%4,%5,%6,%7,%8};"
                 :: "l"(p),
                    "f"(a.x), "f"(a.y), "f"(a.z), "f"(a.w),
                    "f"(b.x), "f"(b.y), "f"(b.z), "f"(b.w)
                 : "memory");
}

// fast acos: Abramowitz-Stegun 4.4.45, |err| <= 6.7e-5 rad
__device__ __forceinline__ float angular_weight(float c) {
    float ax = fabsf(c);
    float s = sqrtf(fmaxf(1.f - ax, 0.f));
    float p = s * (1.5707288f + ax * (-0.2121144f + ax * (0.0742610f - ax * 0.0187293f)));
    float ac = (c >= 0.f) ? p : (3.14159265358979f - p);
    return 1.f - ac * 0.31830988618379067f;
}

// ---------------- band_fused: everything band-related, self-contained per block ----------------
__global__ __launch_bounds__(256)
void band_fused_kernel(const float* __restrict__ x,
                       const float* __restrict__ qmask,
                       const int* __restrict__ dia_len,
                       float* __restrict__ out,
                       int B, int S, int NSPK) {
    extern __shared__ float smem[];
    float* sx    = smem;                       // LR * RPAD normalized rows
    float* sdot  = sx + LR * RPAD;             // SR * 15 forward dots
    float* sband = sdot + SR * WIN;            // CR * 31 band values
    float* sdinv = sband + CR * WW;            // DR
    int*   sspk  = (int*)(sdinv + DR);         // LR

    int b  = blockIdx.y;
    int i0 = blockIdx.x * CR;
    int base = b * S;
    int len = dia_len[b];
    int g0 = i0 - 2 * WIN;                     // first loaded global row

    int lane = threadIdx.x & 31;
    int warp = threadIdx.x >> 5;

    float4* sx4 = (float4*)sx;
    const float4* x4g = (const float4*)(x + (size_t)base * DD);

    // ---- Phase A: load + normalize LR rows (8 thr/row, shfl warp-converged) ----
    {
        int sub = threadIdx.x & 7;
        int rbase = threadIdx.x >> 3;          // 0..31
#pragma unroll
        for (int pass = 0; pass < 4; pass++) {
            int r = pass * 32 + rbase;         // 0..127
            int gr = g0 + r;
            bool inb = (r < LR) && (gr >= 0) && (gr < S);
            float4 v[4];
            float ss = 0.f;
            if (inb) {
#pragma unroll
                for (int k = 0; k < 4; k++) {
                    v[k] = x4g[(size_t)gr * (DD/4) + sub * 4 + k];
                    ss += v[k].x * v[k].x + v[k].y * v[k].y
                        + v[k].z * v[k].z + v[k].w * v[k].w;
                }
            } else {
#pragma unroll
                for (int k = 0; k < 4; k++) v[k] = make_float4(0.f, 0.f, 0.f, 0.f);
            }
#pragma unroll
            for (int off = 4; off; off >>= 1)
                ss += __shfl_xor_sync(0xffffffffu, ss, off);
            float inv = 1.f / fmaxf(sqrtf(ss), 1e-8f);
            if (r < LR) {
#pragma unroll
                for (int k = 0; k < 4; k++) {
                    v[k].x *= inv; v[k].y *= inv; v[k].z *= inv; v[k].w *= inv;
                    sx4[r * RP4 + sub * 4 + k] = v[k];
                }
            }
        }
        // speakers for all loaded rows
        if (threadIdx.x < LR) {
            int gr = g0 + threadIdx.x;
            int bi = -1;
            if (gr >= 0 && gr < S) {
                const float* q = qmask + ((size_t)gr * B + b) * NSPK;
                float best = q[0]; bi = 0;
                for (int k = 1; k < NSPK; k++) {
                    float vq = q[k];
                    if (vq > best) { best = vq; bi = k; }   // JAX first-max
                }
            }
            sspk[threadIdx.x] = bi;
        }
    }
    __syncthreads();

    // ---- Phase B: forward dots. sdot[p][o] = dot(sx row p, sx row p+1+o) ----
    {
        int half = lane >> 4;
        int o = lane & 15;
#pragma unroll
        for (int it = 0; it < 7; it++) {
            int p = it * 16 + warp * 2 + half;     // 0..111
            bool act = (p < SR) && (o < 15);
            int pc  = act ? p : 0;
            int rjc = act ? (p + 1 + o) : 0;       // <= 123 < LR when active
            float dot = 0.f;
            const float4* xi4 = sx4 + pc * RP4;
            const float4* xj4 = sx4 + rjc * RP4;
#pragma unroll
            for (int k = 0; k < DD/4; k++) {
                float4 a4 = xi4[k];
                float4 b4 = xj4[k];
                dot += a4.x * b4.x + a4.y * b4.y + a4.z * b4.z + a4.w * b4.w;
            }
            if (act) sdot[p * WIN + o] = dot;
        }
    }
    __syncthreads();

    // ---- Phase C: deg/dinv for DR rows; band values for central CR rows ----
    {
#pragma unroll
        for (int it = 0; it < 12; it++) {
            int gl = it * 8 + warp;                // 0..95
            if (gl >= DR) continue;                // whole-warp skip, no sync inside
            int g = i0 - WIN + gl;                 // global row i
            int sxr = gl + WIN;                    // sx/sdot row of g
            bool valid_i = (g >= 0) && (g < S) && (g < len);
            int spk_i = sspk[sxr];

            int j = g - WIN + lane;
            int sxj = gl + lane;                   // sx row of j (<= 123)
            bool inr = (lane < WW) && (j >= 0) && (j < S);

            float dot = 0.f;
            if (lane < WIN) {
                if (j >= 0) dot = sdot[(gl + lane) * WIN + (14 - lane)];  // row <= 107 < SR
            } else if (lane == WIN) {
                dot = 1.f;                         // diagonal
            } else if (lane < WW) {
                dot = sdot[sxr * WIN + (lane - 16)];                      // row <= 108 < SR
            }

            bool valid_j = valid_i && inr && (j < len);
            bool same = valid_j && (sspk[sxj] == spk_i);
            int cnt = __popc(__ballot_sync(0xffffffffu, same));

            float a = 0.f;
            if (valid_j) {
                float c = fminf(fmaxf(dot, -1.f), 1.f);
                a = angular_weight(c) * ((cnt > 1 && same) ? 2.f : 1.f);
            }

            float deg = a;
#pragma unroll
            for (int off = 16; off; off >>= 1)
                deg += __shfl_xor_sync(0xffffffffu, deg, off);

            if (gl >= WIN && gl < WIN + CR && lane < WW)
                sband[(gl - WIN) * WW + lane] = a;
            if (lane == 0)
                sdinv[gl] = (deg > 0.f) ? rsqrtf(deg) : 1.f;
        }
    }
    __syncthreads();

    // ---- Phase D: patch the CR band regions (disjoint 32B sectors vs zero fill) ----
    {
#pragma unroll
        for (int it = 0; it < 8; it++) {
            int c = it * 8 + warp;                 // 0..63
            int i = i0 + c;
            int jstart = max(i - WIN, 0);
            int jend   = min(i + WIN, S - 1);
            int p0 = jstart & ~7;
            int p1 = (jend & ~7) + 7;
            float di = sdinv[c + WIN];
            float* orow = out + ((size_t)base + i) * S;
#pragma unroll
            for (int pass = 0; pass < 2; pass++) {
                int j2 = p0 + pass * 32 + lane;
                if (j2 <= p1) {
                    int d = j2 - (i - WIN);
                    float v = 0.f;
                    if (d >= 0 && d < WW)
                        v = sband[c * WW + d] * di * sdinv[c + d];
                    orow[j2] = v;
                }
            }
        }
    }
}

// ---------------- zero_rows: block-per-row zero writer, skips band chunks ----------------
__global__ __launch_bounds__(256)
void zero_rows_kernel(float* __restrict__ out, int B, int S) {
    int row = blockIdx.x;
    int i = row % S;
    float* orow = out + (size_t)row * S;

    int clo = max(i - WIN, 0) >> 3;
    int chi = min(i + WIN, S - 1) >> 3;

    const float4 z = make_float4(0.f, 0.f, 0.f, 0.f);
    int nch = S >> 3;
    for (int c = threadIdx.x; c < nch; c += blockDim.x) {
        if (c < clo || c > chi)
            stg256_cs(orow + (c << 3), z, z);
    }
}

extern "C" void kernel_launch(void* const* d_in, const int* in_sizes, int n_in,
                              void* d_out, int out_size) {
    const float* x       = (const float*)d_in[0];
    const float* qmask   = (const float*)d_in[1];
    const int*   dia_len = (const int*)d_in[2];
    float* out = (float*)d_out;

    int B = in_sizes[2];
    int S = in_sizes[0] / (B * DD);
    int NSPK = in_sizes[1] / (B * S);
    int n = B * S;

    static cudaStream_t s2 = nullptr;
    static cudaEvent_t e_fork = nullptr, e_join = nullptr;
    if (!s2) {
        cudaStreamCreateWithFlags(&s2, cudaStreamNonBlocking);
        cudaEventCreateWithFlags(&e_fork, cudaEventDisableTiming);
        cudaEventCreateWithFlags(&e_join, cudaEventDisableTiming);
        cudaFuncSetAttribute(band_fused_kernel,
                             cudaFuncAttributeMaxDynamicSharedMemorySize, SMEM_BYTES);
    }

    // fork: band_fused launched FIRST so its 256 fat blocks land immediately;
    // zero's smem-free blocks co-schedule in the leftover thread slots.
    cudaEventRecord(e_fork, 0);
    cudaStreamWaitEvent(s2, e_fork, 0);

    dim3 bgrid(S / CR, B);
    band_fused_kernel<<<bgrid, 256, SMEM_BYTES, s2>>>(x, qmask, dia_len, out, B, S, NSPK);
    cudaEventRecord(e_join, s2);

    zero_rows_kernel<<<n, 256>>>(out, B, S);

    cudaStreamWaitEvent(0, e_join, 0);
}